// round 10
// baseline (speedup 1.0000x reference)
#include <cuda_runtime.h>
#include <cstdint>

// ---------------------------------------------------------------------------
// KeyedGRU  (B=64, T=2048, I=H=256, KB=4, KL=16)  -- all fp32
// A: gi GEMM (unchanged, ~1.06ms).
// B: key scan (unchanged, validated).
// C: main scan v4 -- row-partitioned dataflow (R9) with the SYNC PROTOCOL
//    replaced by the validated kB pattern: plain st.shared::cluster
//    broadcasts + ONE barrier.cluster per step. No mbarriers, no st.async,
//    no per-message complete_tx accounting (R7-R9 invariant suspect).
//    Remote addresses mapa'd once before the loop.
// ---------------------------------------------------------------------------

#define T_STEPS 2048
#define BATCH   64
#define HID     256
#define ROWS_MAIN (T_STEPS * BATCH)
#define ROWS_ALL  (ROWS_MAIN + 64)
#define CSIZE 4
#define RPC   192
#define WS    260

__device__ float g_gi[(size_t)ROWS_ALL * 768];
__device__ float g_gates[16 * HID];

typedef unsigned long long ull;

// ---------------- helpers ----------------
__device__ __forceinline__ uint32_t smem_u32(const void* p) {
    uint32_t a;
    asm("{ .reg .u64 t; cvta.to.shared.u64 t, %1; cvt.u32.u64 %0, t; }"
        : "=r"(a) : "l"(p));
    return a;
}
__device__ __forceinline__ void st_cluster_f32(uint32_t laddr, uint32_t rank, float v) {
    uint32_t ra;
    asm volatile("mapa.shared::cluster.u32 %0, %1, %2;" : "=r"(ra) : "r"(laddr), "r"(rank));
    asm volatile("st.shared::cluster.f32 [%0], %1;" :: "r"(ra), "f"(v) : "memory");
}
__device__ __forceinline__ uint32_t mapa_addr(uint32_t laddr, uint32_t rank) {
    uint32_t ra;
    asm("mapa.shared::cluster.u32 %0, %1, %2;" : "=r"(ra) : "r"(laddr), "r"(rank));
    return ra;
}
// plain remote SMEM store of 2 floats (address pre-mapa'd)
__device__ __forceinline__ void st_cluster_2f_pre(uint32_t ra, float a, float b) {
    asm volatile("{ .reg .b64 d; mov.b64 d, {%1, %2};\n\t"
                 "st.shared::cluster.b64 [%0], d; }"
                 :: "r"(ra), "f"(a), "f"(b) : "memory");
}
__device__ __forceinline__ void cluster_sync_() {
    asm volatile("barrier.cluster.arrive.aligned;" ::: "memory");
    asm volatile("barrier.cluster.wait.aligned;" ::: "memory");
}
__device__ __forceinline__ uint32_t ctarank() {
    uint32_t r; asm("mov.u32 %0, %%cluster_ctarank;" : "=r"(r)); return r;
}
__device__ __forceinline__ ull dup2(float a) {
    ull d; asm("mov.b64 %0, {%1, %1};" : "=l"(d) : "f"(a)); return d;
}
__device__ __forceinline__ void fma2(ull& c, ull a, ull b) {
    asm("fma.rn.f32x2 %0, %1, %2, %0;" : "+l"(c) : "l"(a), "l"(b));
}
__device__ __forceinline__ void unpk(ull v, float& x, float& y) {
    asm("mov.b64 {%0, %1}, %2;" : "=f"(x), "=f"(y) : "l"(v));
}
__device__ __forceinline__ float sigm_(float x)  { return 1.0f / (1.0f + __expf(-x)); }
__device__ __forceinline__ float tanh_(float x)  { return 1.0f - __fdividef(2.0f, __expf(2.0f * x) + 1.0f); }
__device__ __forceinline__ float sigmoidf_(float x) { return 1.0f / (1.0f + expf(-x)); }

// ---------------------------------------------------------------------------
// Kernel A: unchanged.
// ---------------------------------------------------------------------------
#define BR2 132

__global__ void __launch_bounds__(256, 2) kA(const float* __restrict__ x,
                                             const float* __restrict__ wmk,
                                             const float* __restrict__ wih,
                                             const float* __restrict__ bih)
{
    extern __shared__ __align__(16) float smA[];
    float (*As)[32][BR2] = (float (*)[32][BR2])smA;
    float (*Bs)[32][BR2] = (float (*)[32][BR2])(smA + 2 * 32 * BR2);

    const int tid = threadIdx.x;
    const int nt = blockIdx.x;
    const int rt = blockIdx.y;
    const int tx = tid & 15, ty = tid >> 4;
    const int m_base = rt * 128, n_base = nt * 128;

    ull acc[8][4];
    #pragma unroll
    for (int i = 0; i < 8; ++i)
        #pragma unroll
        for (int j = 0; j < 4; ++j) acc[i][j] = 0ull;

    float4 ra[4], rb[4];

    auto load_regs = [&](int kc) {
        const int kb = kc * 32;
        #pragma unroll
        for (int q = 0; q < 4; ++q) {
            int v = tid + q * 256;
            int m = v >> 3;
            int k4 = (v & 7) << 2;
            int row = m_base + m;
            if (row < ROWS_MAIN) {
                int t = row >> 6, b = row & 63;
                ra[q] = *(const float4*)&x[((size_t)b * T_STEPS + t) * 256 + kb + k4];
            } else if (row < ROWS_ALL) {
                int r2 = row - ROWS_MAIN;
                int l = r2 >> 2, kbk = r2 & 3;
                ra[q] = *(const float4*)&wmk[((size_t)kbk * 16 + l) * 256 + kb + k4];
            } else {
                ra[q] = make_float4(0.f, 0.f, 0.f, 0.f);
            }
            rb[q] = *(const float4*)&wih[(size_t)(n_base + m) * 256 + kb + k4];
        }
    };

    auto store_stage = [&](int buf) {
        #pragma unroll
        for (int q = 0; q < 4; ++q) {
            int v = tid + q * 256;
            int m = v >> 3;
            int k4 = (v & 7) << 2;
            const float* av = &ra[q].x;
            const float* bv = &rb[q].x;
            #pragma unroll
            for (int j = 0; j < 4; ++j) {
                As[buf][k4 + j][m] = av[j];
                Bs[buf][k4 + j][m] = bv[j];
            }
        }
    };

    load_regs(0);
    store_stage(0);
    __syncthreads();

    for (int kc = 0; kc < 8; ++kc) {
        if (kc < 7) load_regs(kc + 1);
        const int buf = kc & 1;
        #pragma unroll 8
        for (int k = 0; k < 32; ++k) {
            float4 a0 = *(const float4*)&As[buf][k][ty * 8 + 0];
            float4 a1 = *(const float4*)&As[buf][k][ty * 8 + 4];
            ulonglong2 b0 = *(const ulonglong2*)&Bs[buf][k][tx * 4];
            ulonglong2 b1 = *(const ulonglong2*)&Bs[buf][k][64 + tx * 4];
            ull ad[8];
            ad[0] = dup2(a0.x); ad[1] = dup2(a0.y); ad[2] = dup2(a0.z); ad[3] = dup2(a0.w);
            ad[4] = dup2(a1.x); ad[5] = dup2(a1.y); ad[6] = dup2(a1.z); ad[7] = dup2(a1.w);
            #pragma unroll
            for (int i = 0; i < 8; ++i) {
                fma2(acc[i][0], ad[i], b0.x);
                fma2(acc[i][1], ad[i], b0.y);
                fma2(acc[i][2], ad[i], b1.x);
                fma2(acc[i][3], ad[i], b1.y);
            }
        }
        if (kc < 7) {
            store_stage((kc + 1) & 1);
            __syncthreads();
        }
    }

    float4 bs0 = *(const float4*)&bih[n_base + tx * 4];
    float4 bs1 = *(const float4*)&bih[n_base + 64 + tx * 4];
    #pragma unroll
    for (int i = 0; i < 8; ++i) {
        int row = m_base + ty * 8 + i;
        if (row >= ROWS_ALL) break;
        float f0, f1, f2, f3;
        unpk(acc[i][0], f0, f1); unpk(acc[i][1], f2, f3);
        float4 o0 = make_float4(f0 + bs0.x, f1 + bs0.y, f2 + bs0.z, f3 + bs0.w);
        *(float4*)&g_gi[(size_t)row * 768 + n_base + tx * 4] = o0;
        unpk(acc[i][2], f0, f1); unpk(acc[i][3], f2, f3);
        float4 o1 = make_float4(f0 + bs1.x, f1 + bs1.y, f2 + bs1.z, f3 + bs1.w);
        *(float4*)&g_gi[(size_t)row * 768 + n_base + 64 + tx * 4] = o1;
    }
}

// ---------------------------------------------------------------------------
// Kernel B: key scan -- unchanged (validated).
// ---------------------------------------------------------------------------
__global__ void __launch_bounds__(256, 1) __cluster_dims__(CSIZE, 1, 1)
kB(const float* __restrict__ whh, const float* __restrict__ bhh)
{
    extern __shared__ __align__(16) float sm[];
    float* ws   = sm;
    float* hsh  = ws + RPC * WS;
    float* ghx  = hsh + 4 * HID;
    float* rbuf = ghx + 3 * 4 * 64;

    const int tid = threadIdx.x;
    const uint32_t rank = ctarank();

    for (int i = tid; i < RPC * 64; i += 256) {
        int r = i >> 6;
        int k4 = (i & 63) << 2;
        *(float4*)&ws[r * WS + k4] =
            *(const float4*)&whh[((size_t)(rank * RPC + r)) * 256 + k4];
    }
    for (int i = tid; i < 4 * HID; i += 256) hsh[i] = 0.0f;

    const uint32_t hsh_a = smem_u32(hsh);
    const uint32_t ghx_a = smem_u32(ghx);
    cluster_sync_();

    const int hl = tid & 63;
    const int bb = tid >> 6;
    const int hg = (int)rank * 64 + hl;

    for (int t = 0; t < 16; ++t) {
        float ir, ii, inn;
        {
            size_t row = (size_t)(ROWS_MAIN + t * 4 + bb);
            const float* gp = &g_gi[row * 768];
            ir = gp[hg]; ii = gp[256 + hg]; inn = gp[512 + hg];
        }
        if (tid < RPC) {
            const int rg = (int)rank * RPC + tid;
            float acc[4];
            const float bv = bhh[rg];
            #pragma unroll
            for (int b = 0; b < 4; ++b) acc[b] = bv;
            const float* wr = &ws[tid * WS];
            #pragma unroll 4
            for (int k = 0; k < 256; k += 4) {
                float4 w = *(const float4*)&wr[k];
                #pragma unroll
                for (int b = 0; b < 4; ++b) {
                    float4 h4 = *(const float4*)&hsh[b * HID + k];
                    acc[b] += w.x * h4.x + w.y * h4.y + w.z * h4.z + w.w * h4.w;
                }
            }
            const int chunk = rg >> 8;
            const int hv = rg & 255;
            const uint32_t owner = (uint32_t)(hv >> 6);
            const int hvl = hv & 63;
            #pragma unroll
            for (int b = 0; b < 4; ++b) {
                uint32_t addr = ghx_a + (uint32_t)(((chunk * 4 + b) * 64 + hvl) * 4);
                st_cluster_f32(addr, owner, acc[b]);
            }
        }
        cluster_sync_();
        {
            float hr = ghx[(0 * 4 + bb) * 64 + hl];
            float hi = ghx[(1 * 4 + bb) * 64 + hl];
            float hn = ghx[(2 * 4 + bb) * 64 + hl];
            float r = sigmoidf_(ir + hr);
            float z = sigmoidf_(ii + hi);
            float n = tanhf(inn + r * hn);
            float hold = hsh[bb * HID + hg];
            float hy = n + z * (hold - n);
            rbuf[bb * 64 + hl] = r;
            uint32_t addr = hsh_a + (uint32_t)((bb * HID + hg) * 4);
            #pragma unroll
            for (uint32_t rk = 0; rk < CSIZE; ++rk)
                st_cluster_f32(addr, rk, hy);
        }
        __syncthreads();
        if (tid < 64) {
            float s = 0.f;
            #pragma unroll
            for (int b = 0; b < 4; ++b) s += rbuf[b * 64 + tid];
            g_gates[t * 256 + (int)rank * 64 + tid] = s * 0.25f;
        }
        cluster_sync_();
    }
}

// ---------------------------------------------------------------------------
// Kernel C v4: row-partitioned, plain DSMEM stores + one barrier.cluster/step.
// 512 threads = (vl 64) x (ks 8). Thread holds weights for rows
// {vl, 256+vl, 512+vl} (row offset 64*rank), k in [ks*32, ks*32+32).
// Step: prefetch gi (overlaps FFMA) -> FFMA over hbuf[t&1] (complete at entry
// by previous step's barrier) -> STS red -> __syncthreads -> tid<64: reduce,
// GRU, STG out, st.shared::cluster hy into hbuf[(t&1)^1] of all 4 ranks
// (addresses pre-mapa'd) -> barrier.cluster (release/acquire).
// ---------------------------------------------------------------------------
__global__ void __launch_bounds__(512, 1) __cluster_dims__(CSIZE, 1, 1)
kC(const float* __restrict__ whh, const float* __restrict__ bhh,
   float* __restrict__ out)
{
    __shared__ __align__(16) float hbuf[2][2][256];   // [parity][batch][h]
    __shared__ __align__(16) float red[6][8][64];     // [g*2+b][ks][vl]

    const int tid = threadIdx.x;
    const uint32_t rank = ctarank();
    const int cl = blockIdx.x >> 2;
    const int vl = tid & 63;
    const int ks = tid >> 6;

    // weights: rows g*256 + 64*rank + vl, k = ks*32 + [0,32)
    ull wreg[3][16];
    {
        #pragma unroll
        for (int g = 0; g < 3; ++g) {
            const float* wr = whh + ((size_t)(g * 256 + 64 * (int)rank + vl)) * 256 + ks * 32;
            #pragma unroll
            for (int i = 0; i < 32; i += 4) {
                ulonglong2 v = *(const ulonglong2*)&wr[i];
                wreg[g][i / 2]     = v.x;
                wreg[g][i / 2 + 1] = v.y;
            }
        }
    }

    // init hbuf[0] (t=0 reads zeros)
    hbuf[0][tid >> 8][tid & 255] = 0.0f;

    // epilogue constants (tid < 64): eb = batch, eu = h-pair index
    const int eb = tid >> 5;
    const int eu = tid & 31;
    const int hg0 = 64 * (int)rank + 2 * eu;
    const int b_glob = cl * 2 + eb;

    // pre-mapa destination addresses: hbuf[p][eb][hg0] in each rank
    const uint32_t hbuf_a = smem_u32(&hbuf[0][0][0]);
    uint32_t hb_ra[2][CSIZE];
    #pragma unroll
    for (int p = 0; p < 2; ++p) {
        uint32_t lofs = hbuf_a + (uint32_t)(((p * 2 + eb) * 256 + hg0) * 4);
        #pragma unroll
        for (uint32_t rk = 0; rk < CSIZE; ++rk)
            hb_ra[p][rk] = mapa_addr(lofs, rk);
    }

    cluster_sync_();   // hbuf[0] zeroed everywhere

    for (int t = 0; t < T_STEPS; ++t) {
        const int p = t & 1;

        // ---- prefetch gi, biases, gate (tid<64) -- overlaps FFMA below ----
        float2 gir, gii, gin, ggp, bhr, bhi, bhn;
        if (tid < 64) {
            const float* gp = &g_gi[((size_t)t * BATCH + b_glob) * 768 + hg0];
            gir = *(const float2*)&gp[0];
            gii = *(const float2*)&gp[256];
            gin = *(const float2*)&gp[512];
            bhr = *(const float2*)&bhh[hg0];
            bhi = *(const float2*)&bhh[256 + hg0];
            bhn = *(const float2*)&bhh[512 + hg0];
            ggp = make_float2(1.0f, 1.0f);
            if (t < 16) ggp = *(const float2*)&g_gates[t * 256 + hg0];
        }

        // ---- full-k partial for this thread's 3 rows x 2 batches ----
        // hbuf[p] is complete at loop entry (previous step's cluster barrier)
        ull acc[3][2];
        #pragma unroll
        for (int g = 0; g < 3; ++g) { acc[g][0] = 0ull; acc[g][1] = 0ull; }
        {
            const float* h0p = &hbuf[p][0][ks * 32];
            const float* h1p = &hbuf[p][1][ks * 32];
            #pragma unroll
            for (int i = 0; i < 32; i += 4) {
                ulonglong2 h0 = *(const ulonglong2*)&h0p[i];
                ulonglong2 h1 = *(const ulonglong2*)&h1p[i];
                #pragma unroll
                for (int g = 0; g < 3; ++g) {
                    ull wa = wreg[g][i / 2], wb2 = wreg[g][i / 2 + 1];
                    fma2(acc[g][0], wa, h0.x); fma2(acc[g][0], wb2, h0.y);
                    fma2(acc[g][1], wa, h1.x); fma2(acc[g][1], wb2, h1.y);
                }
            }
        }
        #pragma unroll
        for (int g = 0; g < 3; ++g) {
            float x0, y0, x1, y1;
            unpk(acc[g][0], x0, y0);
            unpk(acc[g][1], x1, y1);
            red[g * 2 + 0][ks][vl] = x0 + y0;
            red[g * 2 + 1][ks][vl] = x1 + y1;
        }
        __syncthreads();

        // ---- epilogue (tid<64): reduce 8 slices, 2 GRU cells, broadcast ----
        if (tid < 64) {
            float2 sr = make_float2(0.f, 0.f), si = sr, sn = sr;
            #pragma unroll
            for (int k = 0; k < 8; ++k) {
                float2 a = *(const float2*)&red[0 * 2 + eb][k][2 * eu];
                float2 b = *(const float2*)&red[1 * 2 + eb][k][2 * eu];
                float2 c = *(const float2*)&red[2 * 2 + eb][k][2 * eu];
                sr.x += a.x; sr.y += a.y;
                si.x += b.x; si.y += b.y;
                sn.x += c.x; sn.y += c.y;
            }
            float2 hold = *(const float2*)&hbuf[p][eb][hg0];
            float r0 = sigm_(gir.x + bhr.x + sr.x);
            float r1 = sigm_(gir.y + bhr.y + sr.y);
            float z0 = sigm_(gii.x + bhi.x + si.x);
            float z1 = sigm_(gii.y + bhi.y + si.y);
            float n0 = tanh_(gin.x + r0 * (bhn.x + sn.x));
            float n1 = tanh_(gin.y + r1 * (bhn.y + sn.y));
            float hy0 = n0 + z0 * (hold.x - n0);
            float hy1 = n1 + z1 * (hold.y - n1);
            *(float2*)&out[((size_t)t * BATCH + b_glob) * HID + hg0] =
                make_float2(hy0, hy1);
            hy0 *= ggp.x;
            hy1 *= ggp.y;
            #pragma unroll
            for (uint32_t rk = 0; rk < CSIZE; ++rk)
                st_cluster_2f_pre(hb_ra[p ^ 1][rk], hy0, hy1);
        }

        // one cluster barrier per step: releases our broadcasts, acquires
        // everyone else's; also protects hbuf[p] WAR for step t+1's writers.
        cluster_sync_();
    }
}

// ---------------------------------------------------------------------------
extern "C" void kernel_launch(void* const* d_in, const int* in_sizes, int n_in,
                              void* d_out, int out_size)
{
    const float* x   = (const float*)d_in[0];
    const float* wmk = (const float*)d_in[1];
    const float* wih = (const float*)d_in[2];
    const float* whh = (const float*)d_in[3];
    const float* bih = (const float*)d_in[4];
    const float* bhh = (const float*)d_in[5];
    float* out = (float*)d_out;

    constexpr int SMEM_A   = 2 * 2 * 32 * BR2 * 4;
    constexpr int SMEM_KEY = (RPC * WS + 4 * HID + 3 * 4 * 64 + 4 * 64) * 4;

    cudaFuncSetAttribute((const void*)kA,
                         cudaFuncAttributeMaxDynamicSharedMemorySize, SMEM_A);
    cudaFuncSetAttribute((const void*)kB,
                         cudaFuncAttributeMaxDynamicSharedMemorySize, SMEM_KEY);

    dim3 gA(6, 1025);
    kA<<<gA, 256, SMEM_A>>>(x, wmk, wih, bih);
    kB<<<CSIZE, 256, SMEM_KEY>>>(whh, bhh);
    kC<<<32 * CSIZE, 512>>>(whh, bhh, out);
}

// round 11
// speedup vs baseline: 1.3158x; 1.3158x over previous
#include <cuda_runtime.h>
#include <cstdint>

// ---------------------------------------------------------------------------
// KeyedGRU  (B=64, T=2048, I=H=256, KB=4, KL=16)  -- all fp32
// A: gi GEMM v2 -- 128x256 tile, 8m x 16n microtile, 1 CTA/SM (~200 regs),
//    64 FFMA2 per 6 LDS + 8 dup per k  (2x ILP vs v1; latency-bound fix).
// B: key scan  (R7, validated).
// C: main scan (R7 k-partitioned mbarrier protocol, byte-identical; best
//    measured of 5 designs at ~2.8 ms).
// ---------------------------------------------------------------------------

#define T_STEPS 2048
#define BATCH   64
#define HID     256
#define ROWS_MAIN (T_STEPS * BATCH)
#define ROWS_ALL  (ROWS_MAIN + 64)
#define CSIZE 4
#define RPC   192
#define WS    260

__device__ float g_gi[(size_t)ROWS_ALL * 768];
__device__ float g_gates[16 * HID];

typedef unsigned long long ull;

// ---------------- helpers ----------------
__device__ __forceinline__ uint32_t smem_u32(const void* p) {
    uint32_t a;
    asm("{ .reg .u64 t; cvta.to.shared.u64 t, %1; cvt.u32.u64 %0, t; }"
        : "=r"(a) : "l"(p));
    return a;
}
__device__ __forceinline__ void st_cluster_f32(uint32_t laddr, uint32_t rank, float v) {
    uint32_t ra;
    asm volatile("mapa.shared::cluster.u32 %0, %1, %2;" : "=r"(ra) : "r"(laddr), "r"(rank));
    asm volatile("st.shared::cluster.f32 [%0], %1;" :: "r"(ra), "f"(v) : "memory");
}
__device__ __forceinline__ uint32_t mapa_addr(uint32_t laddr, uint32_t rank) {
    uint32_t ra;
    asm("mapa.shared::cluster.u32 %0, %1, %2;" : "=r"(ra) : "r"(laddr), "r"(rank));
    return ra;
}
__device__ __forceinline__ void st_async_2f(uint32_t ra, float a, float b, uint32_t rbar) {
    asm volatile("{ .reg .b64 d; mov.b64 d, {%1, %2};\n\t"
                 "st.async.shared::cluster.mbarrier::complete_tx::bytes.b64 [%0], d, [%3]; }"
                 :: "r"(ra), "f"(a), "f"(b), "r"(rbar) : "memory");
}
__device__ __forceinline__ void mbar_init(uint32_t a, uint32_t cnt) {
    asm volatile("mbarrier.init.shared.b64 [%0], %1;" :: "r"(a), "r"(cnt) : "memory");
}
__device__ __forceinline__ void mbar_arrive_expect(uint32_t a, uint32_t tx) {
    asm volatile("mbarrier.arrive.expect_tx.shared.b64 _, [%0], %1;"
                 :: "r"(a), "r"(tx) : "memory");
}
__device__ __forceinline__ void mbar_wait_parity(uint32_t mbar, uint32_t parity) {
    uint32_t done;
    asm volatile("{\n\t.reg .pred p;\n\t"
                 "mbarrier.try_wait.parity.acquire.cluster.shared::cta.b64 p, [%1], %2;\n\t"
                 "selp.b32 %0, 1, 0, p;\n\t}"
                 : "=r"(done) : "r"(mbar), "r"(parity) : "memory");
    if (!done) {
        asm volatile("{\n\t.reg .pred P1;\n\t"
                     "WAIT_LOOP_%=:\n\t"
                     "mbarrier.try_wait.parity.acquire.cluster.shared::cta.b64 P1, [%0], %1, 0x989680;\n\t"
                     "@P1 bra.uni WAIT_DONE_%=;\n\t"
                     "bra.uni WAIT_LOOP_%=;\n\t"
                     "WAIT_DONE_%=:\n\t}"
                     :: "r"(mbar), "r"(parity) : "memory");
    }
}
__device__ __forceinline__ void cluster_sync_() {
    asm volatile("barrier.cluster.arrive.aligned;" ::: "memory");
    asm volatile("barrier.cluster.wait.aligned;" ::: "memory");
}
__device__ __forceinline__ uint32_t ctarank() {
    uint32_t r; asm("mov.u32 %0, %%cluster_ctarank;" : "=r"(r)); return r;
}
__device__ __forceinline__ ull dup2(float a) {
    ull d; asm("mov.b64 %0, {%1, %1};" : "=l"(d) : "f"(a)); return d;
}
__device__ __forceinline__ void fma2(ull& c, ull a, ull b) {
    asm("fma.rn.f32x2 %0, %1, %2, %0;" : "+l"(c) : "l"(a), "l"(b));
}
__device__ __forceinline__ void unpk(ull v, float& x, float& y) {
    asm("mov.b64 {%0, %1}, %2;" : "=f"(x), "=f"(y) : "l"(v));
}
__device__ __forceinline__ float sigm_(float x)  { return 1.0f / (1.0f + __expf(-x)); }
__device__ __forceinline__ float tanh_(float x)  { return 1.0f - __fdividef(2.0f, __expf(2.0f * x) + 1.0f); }
__device__ __forceinline__ float sigmoidf_(float x) { return 1.0f / (1.0f + expf(-x)); }

// ---------------------------------------------------------------------------
// Kernel A v2: 128m x 256n tile, 8m x 16n per thread, 1 CTA/SM.
// grid (3, 1025), block 256. Double-buffered SMEM (~100 KB).
// ---------------------------------------------------------------------------
#define AR2 132   // As row stride
#define BRW 260   // Bs row stride (256 + 4)

__global__ void __launch_bounds__(256, 1) kA(const float* __restrict__ x,
                                             const float* __restrict__ wmk,
                                             const float* __restrict__ wih,
                                             const float* __restrict__ bih)
{
    extern __shared__ __align__(16) float smA[];
    float (*As)[32][AR2] = (float (*)[32][AR2])smA;                    // [2][32][132]
    float (*Bs)[32][BRW] = (float (*)[32][BRW])(smA + 2 * 32 * AR2);   // [2][32][260]

    const int tid = threadIdx.x;
    const int nt = blockIdx.x;       // 0..2
    const int rt = blockIdx.y;       // 0..1024
    const int tx = tid & 15, ty = tid >> 4;
    const int m_base = rt * 128, n_base = nt * 256;

    ull acc[8][8];
    #pragma unroll
    for (int i = 0; i < 8; ++i)
        #pragma unroll
        for (int j = 0; j < 8; ++j) acc[i][j] = 0ull;

    float4 ra[4], rb[8];

    auto load_regs = [&](int kc) {
        const int kb = kc * 32;
        #pragma unroll
        for (int q = 0; q < 4; ++q) {
            int v = tid + q * 256;
            int m = v >> 3;
            int k4 = (v & 7) << 2;
            int row = m_base + m;
            if (row < ROWS_MAIN) {
                int t = row >> 6, b = row & 63;
                ra[q] = *(const float4*)&x[((size_t)b * T_STEPS + t) * 256 + kb + k4];
            } else if (row < ROWS_ALL) {
                int r2 = row - ROWS_MAIN;
                int l = r2 >> 2, kbk = r2 & 3;
                ra[q] = *(const float4*)&wmk[((size_t)kbk * 16 + l) * 256 + kb + k4];
            } else {
                ra[q] = make_float4(0.f, 0.f, 0.f, 0.f);
            }
        }
        #pragma unroll
        for (int q = 0; q < 8; ++q) {
            int v = tid + q * 256;
            int n = v >> 3;
            int k4 = (v & 7) << 2;
            rb[q] = *(const float4*)&wih[(size_t)(n_base + n) * 256 + kb + k4];
        }
    };

    auto store_stage = [&](int buf) {
        #pragma unroll
        for (int q = 0; q < 4; ++q) {
            int v = tid + q * 256;
            int m = v >> 3;
            int k4 = (v & 7) << 2;
            const float* av = &ra[q].x;
            #pragma unroll
            for (int j = 0; j < 4; ++j) As[buf][k4 + j][m] = av[j];
        }
        #pragma unroll
        for (int q = 0; q < 8; ++q) {
            int v = tid + q * 256;
            int n = v >> 3;
            int k4 = (v & 7) << 2;
            const float* bv = &rb[q].x;
            #pragma unroll
            for (int j = 0; j < 4; ++j) Bs[buf][k4 + j][n] = bv[j];
        }
    };

    load_regs(0);
    store_stage(0);
    __syncthreads();

    for (int kc = 0; kc < 8; ++kc) {
        if (kc < 7) load_regs(kc + 1);
        const int buf = kc & 1;
        #pragma unroll 4
        for (int k = 0; k < 32; ++k) {
            float4 a0 = *(const float4*)&As[buf][k][ty * 8 + 0];
            float4 a1 = *(const float4*)&As[buf][k][ty * 8 + 4];
            ulonglong2 b0 = *(const ulonglong2*)&Bs[buf][k][tx * 8];
            ulonglong2 b1 = *(const ulonglong2*)&Bs[buf][k][tx * 8 + 4];
            ulonglong2 b2 = *(const ulonglong2*)&Bs[buf][k][128 + tx * 8];
            ulonglong2 b3 = *(const ulonglong2*)&Bs[buf][k][128 + tx * 8 + 4];
            ull ad[8];
            ad[0] = dup2(a0.x); ad[1] = dup2(a0.y); ad[2] = dup2(a0.z); ad[3] = dup2(a0.w);
            ad[4] = dup2(a1.x); ad[5] = dup2(a1.y); ad[6] = dup2(a1.z); ad[7] = dup2(a1.w);
            #pragma unroll
            for (int i = 0; i < 8; ++i) {
                fma2(acc[i][0], ad[i], b0.x);
                fma2(acc[i][1], ad[i], b0.y);
                fma2(acc[i][2], ad[i], b1.x);
                fma2(acc[i][3], ad[i], b1.y);
                fma2(acc[i][4], ad[i], b2.x);
                fma2(acc[i][5], ad[i], b2.y);
                fma2(acc[i][6], ad[i], b3.x);
                fma2(acc[i][7], ad[i], b3.y);
            }
        }
        if (kc < 7) {
            store_stage((kc + 1) & 1);
            __syncthreads();
        }
    }

    float4 bs0 = *(const float4*)&bih[n_base + tx * 8];
    float4 bs1 = *(const float4*)&bih[n_base + tx * 8 + 4];
    float4 bs2 = *(const float4*)&bih[n_base + 128 + tx * 8];
    float4 bs3 = *(const float4*)&bih[n_base + 128 + tx * 8 + 4];
    #pragma unroll
    for (int i = 0; i < 8; ++i) {
        int row = m_base + ty * 8 + i;
        if (row >= ROWS_ALL) break;
        float f0, f1, f2, f3;
        float* gp = &g_gi[(size_t)row * 768 + n_base];
        unpk(acc[i][0], f0, f1); unpk(acc[i][1], f2, f3);
        *(float4*)&gp[tx * 8] =
            make_float4(f0 + bs0.x, f1 + bs0.y, f2 + bs0.z, f3 + bs0.w);
        unpk(acc[i][2], f0, f1); unpk(acc[i][3], f2, f3);
        *(float4*)&gp[tx * 8 + 4] =
            make_float4(f0 + bs1.x, f1 + bs1.y, f2 + bs1.z, f3 + bs1.w);
        unpk(acc[i][4], f0, f1); unpk(acc[i][5], f2, f3);
        *(float4*)&gp[128 + tx * 8] =
            make_float4(f0 + bs2.x, f1 + bs2.y, f2 + bs2.z, f3 + bs2.w);
        unpk(acc[i][6], f0, f1); unpk(acc[i][7], f2, f3);
        *(float4*)&gp[128 + tx * 8 + 4] =
            make_float4(f0 + bs3.x, f1 + bs3.y, f2 + bs3.z, f3 + bs3.w);
    }
}

// ---------------------------------------------------------------------------
// Kernel B: key scan -- unchanged (validated).
// ---------------------------------------------------------------------------
__global__ void __launch_bounds__(256, 1) __cluster_dims__(CSIZE, 1, 1)
kB(const float* __restrict__ whh, const float* __restrict__ bhh)
{
    extern __shared__ __align__(16) float sm[];
    float* ws   = sm;
    float* hsh  = ws + RPC * WS;
    float* ghx  = hsh + 4 * HID;
    float* rbuf = ghx + 3 * 4 * 64;

    const int tid = threadIdx.x;
    const uint32_t rank = ctarank();

    for (int i = tid; i < RPC * 64; i += 256) {
        int r = i >> 6;
        int k4 = (i & 63) << 2;
        *(float4*)&ws[r * WS + k4] =
            *(const float4*)&whh[((size_t)(rank * RPC + r)) * 256 + k4];
    }
    for (int i = tid; i < 4 * HID; i += 256) hsh[i] = 0.0f;

    const uint32_t hsh_a = smem_u32(hsh);
    const uint32_t ghx_a = smem_u32(ghx);
    cluster_sync_();

    const int hl = tid & 63;
    const int bb = tid >> 6;
    const int hg = (int)rank * 64 + hl;

    for (int t = 0; t < 16; ++t) {
        float ir, ii, inn;
        {
            size_t row = (size_t)(ROWS_MAIN + t * 4 + bb);
            const float* gp = &g_gi[row * 768];
            ir = gp[hg]; ii = gp[256 + hg]; inn = gp[512 + hg];
        }
        if (tid < RPC) {
            const int rg = (int)rank * RPC + tid;
            float acc[4];
            const float bv = bhh[rg];
            #pragma unroll
            for (int b = 0; b < 4; ++b) acc[b] = bv;
            const float* wr = &ws[tid * WS];
            #pragma unroll 4
            for (int k = 0; k < 256; k += 4) {
                float4 w = *(const float4*)&wr[k];
                #pragma unroll
                for (int b = 0; b < 4; ++b) {
                    float4 h4 = *(const float4*)&hsh[b * HID + k];
                    acc[b] += w.x * h4.x + w.y * h4.y + w.z * h4.z + w.w * h4.w;
                }
            }
            const int chunk = rg >> 8;
            const int hv = rg & 255;
            const uint32_t owner = (uint32_t)(hv >> 6);
            const int hvl = hv & 63;
            #pragma unroll
            for (int b = 0; b < 4; ++b) {
                uint32_t addr = ghx_a + (uint32_t)(((chunk * 4 + b) * 64 + hvl) * 4);
                st_cluster_f32(addr, owner, acc[b]);
            }
        }
        cluster_sync_();
        {
            float hr = ghx[(0 * 4 + bb) * 64 + hl];
            float hi = ghx[(1 * 4 + bb) * 64 + hl];
            float hn = ghx[(2 * 4 + bb) * 64 + hl];
            float r = sigmoidf_(ir + hr);
            float z = sigmoidf_(ii + hi);
            float n = tanhf(inn + r * hn);
            float hold = hsh[bb * HID + hg];
            float hy = n + z * (hold - n);
            rbuf[bb * 64 + hl] = r;
            uint32_t addr = hsh_a + (uint32_t)((bb * HID + hg) * 4);
            #pragma unroll
            for (uint32_t rk = 0; rk < CSIZE; ++rk)
                st_cluster_f32(addr, rk, hy);
        }
        __syncthreads();
        if (tid < 64) {
            float s = 0.f;
            #pragma unroll
            for (int b = 0; b < 4; ++b) s += rbuf[b * 64 + tid];
            g_gates[t * 256 + (int)rank * 64 + tid] = s * 0.25f;
        }
        cluster_sync_();
    }
}

// ---------------------------------------------------------------------------
// Kernel C: R7 k-partitioned design, byte-identical (best measured, ~2.8ms).
// 512 threads, k-half split, wp[3][16] regs, st.async + mbarrier, arm t+2
// after wait, combine-sync + tail-sync per step.
// ---------------------------------------------------------------------------
#define TXB 6144u

__global__ void __launch_bounds__(512, 1) __cluster_dims__(CSIZE, 1, 1)
kC(const float* __restrict__ whh, const float* __restrict__ bhh,
   float* __restrict__ out)
{
    __shared__ __align__(16) float part[2][4][3][64][2];
    __shared__ __align__(16) float hp[2][64];
    __shared__ __align__(16) float red[256][10];
    __shared__ __align__(8) unsigned long long mbar[2];

    const int tid = threadIdx.x;
    const uint32_t rank = ctarank();
    const int cl = blockIdx.x >> 2;
    const int kh = tid >> 8;
    const int hx = tid & 255;
    const int hoff = kh * 32;

    ull wp[3][16];
    {
        const float* wb = whh + (size_t)rank * 64 + hoff;
        #pragma unroll
        for (int j = 0; j < 3; ++j) {
            const float* wr = wb + (size_t)(j * 256 + hx) * 256;
            #pragma unroll
            for (int kk = 0; kk < 32; kk += 4) {
                ulonglong2 v = *(const ulonglong2*)&wr[kk];
                wp[j][kk / 2] = v.x;
                wp[j][kk / 2 + 1] = v.y;
            }
        }
    }

    if (tid < 128) hp[tid >> 6][tid & 63] = 0.0f;

    const uint32_t mb_a = smem_u32(&mbar[0]);
    if (tid == 0) {
        mbar_init(mb_a, 1);
        mbar_init(mb_a + 8, 1);
        mbar_arrive_expect(mb_a, TXB);
        mbar_arrive_expect(mb_a + 8, TXB);
    }

    const uint32_t owner = (uint32_t)(hx >> 6);
    const int hvl = hx & 63;
    const uint32_t part_a = smem_u32(&part[0][0][0][0][0]);
    const uint32_t ra_base = mapa_addr(part_a + (uint32_t)((rank * 384 + hvl * 2) * 4), owner);
    const uint32_t rbar_base = mapa_addr(mb_a, owner);

    const int e_b = tid >> 6;
    const int e_hl = tid & 63;
    const int e_hg = (int)rank * 64 + e_hl;
    float bh_r = 0.f, bh_i = 0.f, bh_n = 0.f;
    if (tid < 128) {
        bh_r = bhh[e_hg];
        bh_i = bhh[256 + e_hg];
        bh_n = bhh[512 + e_hg];
    }
    const int b_glob = cl * 2 + e_b;

    cluster_sync_();

    for (int t = 0; t < T_STEPS; ++t) {
        float ir = 0.f, ii = 0.f, inn = 0.f, gg = 1.f;
        if (tid < 128) {
            const float* gp = &g_gi[((size_t)t * BATCH + b_glob) * 768];
            ir  = gp[e_hg];
            ii  = gp[256 + e_hg];
            inn = gp[512 + e_hg];
            if (t < 16) gg = g_gates[t * 256 + e_hg];
        }

        ull a00 = 0, a01 = 0, a10 = 0, a11 = 0, a20 = 0, a21 = 0;
        #pragma unroll
        for (int kk = 0; kk < 32; kk += 4) {
            ulonglong2 h0 = *(const ulonglong2*)&hp[0][hoff + kk];
            ulonglong2 h1 = *(const ulonglong2*)&hp[1][hoff + kk];
            ull w0a = wp[0][kk / 2], w0b = wp[0][kk / 2 + 1];
            ull w1a = wp[1][kk / 2], w1b = wp[1][kk / 2 + 1];
            ull w2a = wp[2][kk / 2], w2b = wp[2][kk / 2 + 1];
            fma2(a00, w0a, h0.x); fma2(a00, w0b, h0.y);
            fma2(a01, w0a, h1.x); fma2(a01, w0b, h1.y);
            fma2(a10, w1a, h0.x); fma2(a10, w1b, h0.y);
            fma2(a11, w1a, h1.x); fma2(a11, w1b, h1.y);
            fma2(a20, w2a, h0.x); fma2(a20, w2b, h0.y);
            fma2(a21, w2a, h1.x); fma2(a21, w2b, h1.y);
        }
        float s00, s01, s10, s11, s20, s21;
        {
            float x0, y0;
            unpk(a00, x0, y0); s00 = x0 + y0;
            unpk(a01, x0, y0); s01 = x0 + y0;
            unpk(a10, x0, y0); s10 = x0 + y0;
            unpk(a11, x0, y0); s11 = x0 + y0;
            unpk(a20, x0, y0); s20 = x0 + y0;
            unpk(a21, x0, y0); s21 = x0 + y0;
        }

        if (kh == 1) {
            *(float2*)&red[hx][0] = make_float2(s00, s01);
            *(float2*)&red[hx][2] = make_float2(s10, s11);
            *(float2*)&red[hx][4] = make_float2(s20, s21);
        }
        __syncthreads();

        if (kh == 0) {
            const uint32_t pbase = ra_base + (uint32_t)((t & 1) * 6144);
            const uint32_t rb = rbar_base + 8u * (uint32_t)(t & 1);
            float2 o0 = *(const float2*)&red[hx][0];
            float2 o1 = *(const float2*)&red[hx][2];
            float2 o2 = *(const float2*)&red[hx][4];
            st_async_2f(pbase + 0 * 512, s00 + o0.x, s01 + o0.y, rb);
            st_async_2f(pbase + 1 * 512, s10 + o1.x, s11 + o1.y, rb);
            st_async_2f(pbase + 2 * 512, s20 + o2.x, s21 + o2.y, rb);
        }

        mbar_wait_parity(mb_a + 8u * (t & 1), (uint32_t)((t >> 1) & 1));

        if (tid == 0)
            mbar_arrive_expect(mb_a + 8u * (t & 1), TXB);

        if (tid < 128) {
            const int p = t & 1;
            float s_r = bh_r, s_i = bh_i, s_n = bh_n;
            #pragma unroll
            for (int src = 0; src < 4; ++src) {
                s_r += part[p][src][0][e_hl][e_b];
                s_i += part[p][src][1][e_hl][e_b];
                s_n += part[p][src][2][e_hl][e_b];
            }
            float r = sigm_(ir + s_r);
            float z = sigm_(ii + s_i);
            float n = tanh_(inn + r * s_n);
            float hold = hp[e_b][e_hl];
            float hy = n + z * (hold - n);
            out[((size_t)t * BATCH + b_glob) * HID + e_hg] = hy;
            hp[e_b][e_hl] = hy * gg;
        }
        __syncthreads();
    }
}

// ---------------------------------------------------------------------------
extern "C" void kernel_launch(void* const* d_in, const int* in_sizes, int n_in,
                              void* d_out, int out_size)
{
    const float* x   = (const float*)d_in[0];
    const float* wmk = (const float*)d_in[1];
    const float* wih = (const float*)d_in[2];
    const float* whh = (const float*)d_in[3];
    const float* bih = (const float*)d_in[4];
    const float* bhh = (const float*)d_in[5];
    float* out = (float*)d_out;

    constexpr int SMEM_A   = (2 * 32 * AR2 + 2 * 32 * BRW) * 4;  // 100,352 B
    constexpr int SMEM_KEY = (RPC * WS + 4 * HID + 3 * 4 * 64 + 4 * 64) * 4;

    cudaFuncSetAttribute((const void*)kA,
                         cudaFuncAttributeMaxDynamicSharedMemorySize, SMEM_A);
    cudaFuncSetAttribute((const void*)kB,
                         cudaFuncAttributeMaxDynamicSharedMemorySize, SMEM_KEY);

    dim3 gA(3, 1025);
    kA<<<gA, 256, SMEM_A>>>(x, wmk, wih, bih);
    kB<<<CSIZE, 256, SMEM_KEY>>>(whh, bhh);
    kC<<<32 * CSIZE, 512>>>(whh, bhh, out);
}